// round 1
// baseline (speedup 1.0000x reference)
#include <cuda_runtime.h>
#include <cstdint>
#include <math.h>

#define S_DIM 256
#define B_DIM 2048
#define D_DIM 128
#define RET_ELEMS (256LL * 2048LL * 128LL)
#define DIFF_ELEMS (255LL * 2048LL * 128LL)

// ---------------------------------------------------------------------------
// helpers
// ---------------------------------------------------------------------------
__device__ __forceinline__ float gelu_exact(float x) {
    return 0.5f * x * (1.0f + erff(x * 0.7071067811865476f));
}

__device__ __forceinline__ unsigned f2tf32(float x) {
    unsigned r;
    asm("cvt.rna.tf32.f32 %0, %1;" : "=r"(r) : "f"(x));
    return r;
}

__device__ __forceinline__ void mma_m16n8k8(float* d, const unsigned* a, const unsigned* b) {
    asm volatile(
        "mma.sync.aligned.m16n8k8.row.col.f32.tf32.tf32.f32 "
        "{%0,%1,%2,%3}, {%4,%5,%6,%7}, {%8,%9}, {%0,%1,%2,%3};"
        : "+f"(d[0]), "+f"(d[1]), "+f"(d[2]), "+f"(d[3])
        : "r"(a[0]), "r"(a[1]), "r"(a[2]), "r"(a[3]), "r"(b[0]), "r"(b[1]));
}

// ---------------------------------------------------------------------------
// Kernel A: ret = LayerNorm(gelu(gelu(X@W1+b1)@W2+b2) + X)
// CTA tile: 128 tokens (one s, 128 consecutive b), 256 threads = 8 warps.
// Warps arranged 4 (M) x 2 (N). GEMM1 produced in 4 chunks of 64 H-columns,
// each chunk immediately consumed as a K=64 slice of GEMM2.
// ---------------------------------------------------------------------------
__global__ __launch_bounds__(256, 1)
void fused_main_kernel(const float* __restrict__ src,
                       const float* __restrict__ W1, const float* __restrict__ b1,
                       const float* __restrict__ W2, const float* __restrict__ b2,
                       const float* __restrict__ gamma, const float* __restrict__ beta,
                       float* __restrict__ out_ret)
{
    extern __shared__ float sm[];
    float* Xs  = sm;                // [128][132]   16896 floats
    float* Hs  = Xs + 128 * 132;    // [128][68]     8704 floats
    float* Wbf = Hs + 128 * 68;     // 8704 floats (W1 chunk [64][132] or W2 chunk [128][68])
    float* b1s = Wbf + 8704;        // 256
    float* b2s = b1s + 256;         // 128
    float* gs  = b2s + 128;         // 128
    float* bs  = gs + 128;          // 128

    const int tid   = threadIdx.x;
    const int wid   = tid >> 5, lane = tid & 31;
    const int group = lane >> 2, tq = lane & 3;
    const int wm    = wid & 3;   // M block (32 rows)
    const int wn    = wid >> 2;  // N block

    const int s  = blockIdx.y;
    const int b0 = blockIdx.x * 128;
    const float* Xg = src + ((size_t)s * B_DIM + b0) * D_DIM;

    // load X tile (fp32 exact — needed for residual; mma truncation handled per-fragment)
    for (int i = tid; i < 128 * 32; i += 256) {
        int r = i >> 5, c4 = i & 31;
        float4 v = reinterpret_cast<const float4*>(Xg + (size_t)r * D_DIM)[c4];
        *reinterpret_cast<float4*>(&Xs[r * 132 + c4 * 4]) = v;
    }
    b1s[tid] = b1[tid];
    if (tid < 128) { b2s[tid] = b2[tid]; gs[tid] = gamma[tid]; bs[tid] = beta[tid]; }
    __syncthreads();

    float acc[16][4];   // TF accumulator: warp tile 32x64 = 2 mtiles x 8 ntiles
#pragma unroll
    for (int i = 0; i < 16; i++) { acc[i][0] = acc[i][1] = acc[i][2] = acc[i][3] = 0.f; }

    for (int c = 0; c < 4; ++c) {
        // ---- stage W1 chunk: [n=64][k=128], stride 132 ----
        for (int i = tid; i < 64 * 128; i += 256) {
            int k = i >> 6, n = i & 63;
            Wbf[n * 132 + k] = __uint_as_float(f2tf32(W1[k * 256 + c * 64 + n]));
        }
        __syncthreads();

        // ---- GEMM1 sub: Hc = X @ W1c, warp tile 32x32 ----
        float ha[8][4];
#pragma unroll
        for (int i = 0; i < 8; i++) { ha[i][0] = ha[i][1] = ha[i][2] = ha[i][3] = 0.f; }

#pragma unroll
        for (int k0 = 0; k0 < 128; k0 += 8) {
            unsigned afr[2][4];
#pragma unroll
            for (int mt = 0; mt < 2; mt++) {
                int r = wm * 32 + mt * 16 + group;
                afr[mt][0] = f2tf32(Xs[r * 132 + k0 + tq]);
                afr[mt][1] = f2tf32(Xs[(r + 8) * 132 + k0 + tq]);
                afr[mt][2] = f2tf32(Xs[r * 132 + k0 + tq + 4]);
                afr[mt][3] = f2tf32(Xs[(r + 8) * 132 + k0 + tq + 4]);
            }
#pragma unroll
            for (int nt = 0; nt < 4; nt++) {
                int n = wn * 32 + nt * 8 + group;
                unsigned bfr[2];
                bfr[0] = __float_as_uint(Wbf[n * 132 + k0 + tq]);
                bfr[1] = __float_as_uint(Wbf[n * 132 + k0 + tq + 4]);
                mma_m16n8k8(ha[0 * 4 + nt], afr[0], bfr);
                mma_m16n8k8(ha[1 * 4 + nt], afr[1], bfr);
            }
        }
        __syncthreads();   // all GEMM1 reads of Wbf done

        // ---- bias + gelu -> Hs (tf32-rounded, GEMM2 A-operand), stride 68 ----
#pragma unroll
        for (int mt = 0; mt < 2; mt++) {
#pragma unroll
            for (int nt = 0; nt < 4; nt++) {
                int colb = wn * 32 + nt * 8 + 2 * tq;
                float bi0 = b1s[c * 64 + colb], bi1 = b1s[c * 64 + colb + 1];
                int r = wm * 32 + mt * 16 + group;
                float* hv = ha[mt * 4 + nt];
                Hs[r * 68 + colb]           = __uint_as_float(f2tf32(gelu_exact(hv[0] + bi0)));
                Hs[r * 68 + colb + 1]       = __uint_as_float(f2tf32(gelu_exact(hv[1] + bi1)));
                Hs[(r + 8) * 68 + colb]     = __uint_as_float(f2tf32(gelu_exact(hv[2] + bi0)));
                Hs[(r + 8) * 68 + colb + 1] = __uint_as_float(f2tf32(gelu_exact(hv[3] + bi1)));
            }
        }

        // ---- stage W2 chunk: [n=128][k=64], stride 68 ----
        for (int i = tid; i < 64 * 128; i += 256) {
            int k = i >> 7, n = i & 127;
            Wbf[n * 68 + k] = __uint_as_float(f2tf32(W2[(c * 64 + k) * 128 + n]));
        }
        __syncthreads();

        // ---- GEMM2 partial: TF += Hc @ W2c (K=64), warp tile 32x64 ----
#pragma unroll
        for (int k0 = 0; k0 < 64; k0 += 8) {
            unsigned afr[2][4];
#pragma unroll
            for (int mt = 0; mt < 2; mt++) {
                int r = wm * 32 + mt * 16 + group;
                afr[mt][0] = __float_as_uint(Hs[r * 68 + k0 + tq]);
                afr[mt][1] = __float_as_uint(Hs[(r + 8) * 68 + k0 + tq]);
                afr[mt][2] = __float_as_uint(Hs[r * 68 + k0 + tq + 4]);
                afr[mt][3] = __float_as_uint(Hs[(r + 8) * 68 + k0 + tq + 4]);
            }
#pragma unroll
            for (int nt = 0; nt < 8; nt++) {
                int n = wn * 64 + nt * 8 + group;
                unsigned bfr[2];
                bfr[0] = __float_as_uint(Wbf[n * 68 + k0 + tq]);
                bfr[1] = __float_as_uint(Wbf[n * 68 + k0 + tq + 4]);
                mma_m16n8k8(acc[0 * 8 + nt], afr[0], bfr);
                mma_m16n8k8(acc[1 * 8 + nt], afr[1], bfr);
            }
        }
        __syncthreads();   // before next chunk reuses Wbf / Hs
    }

    // ---- epilogue: r = gelu(TF + b2) + X, written in place into Xs ----
#pragma unroll
    for (int mt = 0; mt < 2; mt++) {
#pragma unroll
        for (int nt = 0; nt < 8; nt++) {
            int col = wn * 64 + nt * 8 + 2 * tq;
            int r = wm * 32 + mt * 16 + group;
            float bi0 = b2s[col], bi1 = b2s[col + 1];
            float* av = acc[mt * 8 + nt];
            Xs[r * 132 + col]           = gelu_exact(av[0] + bi0) + Xs[r * 132 + col];
            Xs[r * 132 + col + 1]       = gelu_exact(av[1] + bi1) + Xs[r * 132 + col + 1];
            Xs[(r + 8) * 132 + col]     = gelu_exact(av[2] + bi0) + Xs[(r + 8) * 132 + col];
            Xs[(r + 8) * 132 + col + 1] = gelu_exact(av[3] + bi1) + Xs[(r + 8) * 132 + col + 1];
        }
    }
    __syncthreads();

    // ---- LayerNorm: warp wid handles rows [wid*16, wid*16+16) ----
    float* outg = out_ret + ((size_t)s * B_DIM + b0) * D_DIM;
    for (int rr = 0; rr < 16; ++rr) {
        int row = wid * 16 + rr;
        float4 x = *reinterpret_cast<float4*>(&Xs[row * 132 + lane * 4]);
        float sum = x.x + x.y + x.z + x.w;
        float sq  = x.x * x.x + x.y * x.y + x.z * x.z + x.w * x.w;
#pragma unroll
        for (int o = 16; o; o >>= 1) {
            sum += __shfl_xor_sync(0xffffffffu, sum, o);
            sq  += __shfl_xor_sync(0xffffffffu, sq, o);
        }
        float mu   = sum * (1.0f / 128.0f);
        float var  = sq * (1.0f / 128.0f) - mu * mu;
        float rsig = rsqrtf(var + 1e-5f);
        int col = lane * 4;
        float4 o4;
        o4.x = (x.x - mu) * rsig * gs[col]     + bs[col];
        o4.y = (x.y - mu) * rsig * gs[col + 1] + bs[col + 1];
        o4.z = (x.z - mu) * rsig * gs[col + 2] + bs[col + 2];
        o4.w = (x.w - mu) * rsig * gs[col + 3] + bs[col + 3];
        *reinterpret_cast<float4*>(&outg[(size_t)row * D_DIM + col]) = o4;
    }
}

// ---------------------------------------------------------------------------
// Kernel B: diffs[s-1] = gelu([X_{s-1} | X_s] @ Wb + bb)
// K=256 split into two halves (prev-half, cur-half). Same warp layout as A.
// ---------------------------------------------------------------------------
__global__ __launch_bounds__(256, 1)
void bracket_kernel(const float* __restrict__ src,
                    const float* __restrict__ Wb, const float* __restrict__ bb,
                    float* __restrict__ out_diffs,
                    float* __restrict__ cond)
{
    extern __shared__ float sm[];
    float* Xc  = sm;                 // [128][132]
    float* Xp  = Xc + 16896;         // [128][132]
    float* Wbf = Xp + 16896;         // [128][132]
    float* bbs = Wbf + 16896;        // 128

    const int tid   = threadIdx.x;
    const int wid   = tid >> 5, lane = tid & 31;
    const int group = lane >> 2, tq = lane & 3;
    const int wm    = wid & 3;
    const int wn    = wid >> 2;

    const int s  = blockIdx.y + 1;
    const int b0 = blockIdx.x * 128;

    if (blockIdx.x == 0 && blockIdx.y == 0 && tid < 3) cond[tid] = 0.0f;

    const float* Xgc = src + ((size_t)s * B_DIM + b0) * D_DIM;
    const float* Xgp = src + ((size_t)(s - 1) * B_DIM + b0) * D_DIM;

    for (int i = tid; i < 128 * 32; i += 256) {
        int r = i >> 5, c4 = i & 31;
        *reinterpret_cast<float4*>(&Xp[r * 132 + c4 * 4]) =
            reinterpret_cast<const float4*>(Xgp + (size_t)r * D_DIM)[c4];
        *reinterpret_cast<float4*>(&Xc[r * 132 + c4 * 4]) =
            reinterpret_cast<const float4*>(Xgc + (size_t)r * D_DIM)[c4];
    }
    if (tid < 128) bbs[tid] = bb[tid];

    float acc[16][4];
#pragma unroll
    for (int i = 0; i < 16; i++) { acc[i][0] = acc[i][1] = acc[i][2] = acc[i][3] = 0.f; }

    for (int h = 0; h < 2; ++h) {
        const float* A = h ? Xc : Xp;
        // stage Wb half: rows h*128+k, layout [n=128][k], stride 132
        for (int i = tid; i < 128 * 128; i += 256) {
            int k = i >> 7, n = i & 127;
            Wbf[n * 132 + k] = __uint_as_float(f2tf32(Wb[(h * 128 + k) * 128 + n]));
        }
        __syncthreads();

#pragma unroll
        for (int k0 = 0; k0 < 128; k0 += 8) {
            unsigned afr[2][4];
#pragma unroll
            for (int mt = 0; mt < 2; mt++) {
                int r = wm * 32 + mt * 16 + group;
                afr[mt][0] = f2tf32(A[r * 132 + k0 + tq]);
                afr[mt][1] = f2tf32(A[(r + 8) * 132 + k0 + tq]);
                afr[mt][2] = f2tf32(A[r * 132 + k0 + tq + 4]);
                afr[mt][3] = f2tf32(A[(r + 8) * 132 + k0 + tq + 4]);
            }
#pragma unroll
            for (int nt = 0; nt < 8; nt++) {
                int n = wn * 64 + nt * 8 + group;
                unsigned bfr[2];
                bfr[0] = __float_as_uint(Wbf[n * 132 + k0 + tq]);
                bfr[1] = __float_as_uint(Wbf[n * 132 + k0 + tq + 4]);
                mma_m16n8k8(acc[0 * 8 + nt], afr[0], bfr);
                mma_m16n8k8(acc[1 * 8 + nt], afr[1], bfr);
            }
        }
        __syncthreads();   // before overwriting Wbf (h=1)
    }

    // epilogue: gelu(acc + bb) -> diffs[(s-1), b0+row, col]
    float* og = out_diffs + ((size_t)(s - 1) * B_DIM + b0) * D_DIM;
#pragma unroll
    for (int mt = 0; mt < 2; mt++) {
#pragma unroll
        for (int nt = 0; nt < 8; nt++) {
            int col = wn * 64 + nt * 8 + 2 * tq;
            int r = wm * 32 + mt * 16 + group;
            float bi0 = bbs[col], bi1 = bbs[col + 1];
            float* av = acc[mt * 8 + nt];
            float2 v0 = { gelu_exact(av[0] + bi0), gelu_exact(av[1] + bi1) };
            float2 v1 = { gelu_exact(av[2] + bi0), gelu_exact(av[3] + bi1) };
            *reinterpret_cast<float2*>(&og[(size_t)r * D_DIM + col])       = v0;
            *reinterpret_cast<float2*>(&og[(size_t)(r + 8) * D_DIM + col]) = v1;
        }
    }
}

// ---------------------------------------------------------------------------
// launcher
// ---------------------------------------------------------------------------
extern "C" void kernel_launch(void* const* d_in, const int* in_sizes, int n_in,
                              void* d_out, int out_size)
{
    const float* src   = (const float*)d_in[0];
    const float* Wb    = (const float*)d_in[1];
    const float* bb    = (const float*)d_in[2];
    const float* W1    = (const float*)d_in[3];
    const float* b1    = (const float*)d_in[4];
    const float* W2    = (const float*)d_in[5];
    const float* b2    = (const float*)d_in[6];
    const float* gamma = (const float*)d_in[7];
    const float* beta  = (const float*)d_in[8];
    float* out = (float*)d_out;

    const int smA = (16896 + 8704 + 8704 + 256 + 128 + 128 + 128) * 4;   // 139776 B
    const int smB = (3 * 16896 + 128) * 4;                               // 203264 B

    cudaFuncSetAttribute(fused_main_kernel, cudaFuncAttributeMaxDynamicSharedMemorySize, smA);
    cudaFuncSetAttribute(bracket_kernel,    cudaFuncAttributeMaxDynamicSharedMemorySize, smB);

    dim3 gA(B_DIM / 128, S_DIM);       // (16, 256)
    dim3 gB(B_DIM / 128, S_DIM - 1);   // (16, 255)

    fused_main_kernel<<<gA, 256, smA>>>(src, W1, b1, W2, b2, gamma, beta, out);
    bracket_kernel<<<gB, 256, smB>>>(src, Wb, bb,
                                     out + RET_ELEMS,
                                     out + RET_ELEMS + DIFF_ELEMS);
}

// round 2
// speedup vs baseline: 1.2996x; 1.2996x over previous
#include <cuda_runtime.h>
#include <cstdint>
#include <math.h>

#define RET_ELEMS (256LL * 2048LL * 128LL)
#define DIFF_ELEMS (255LL * 2048LL * 128LL)

// ---------------------------------------------------------------------------
// helpers
// ---------------------------------------------------------------------------
__device__ __forceinline__ float gelu_exact(float x) {
    return 0.5f * x * (1.0f + erff(x * 0.7071067811865476f));
}
__device__ __forceinline__ unsigned f2tf32(float x) {
    unsigned r; asm("cvt.rna.tf32.f32 %0, %1;" : "=r"(r) : "f"(x)); return r;
}
__device__ __forceinline__ float tf32f(float x) { return __uint_as_float(f2tf32(x)); }

__device__ __forceinline__ void mma8(float* d, const unsigned* a, const unsigned* b) {
    asm volatile(
        "mma.sync.aligned.m16n8k8.row.col.f32.tf32.tf32.f32 "
        "{%0,%1,%2,%3}, {%4,%5,%6,%7}, {%8,%9}, {%0,%1,%2,%3};"
        : "+f"(d[0]), "+f"(d[1]), "+f"(d[2]), "+f"(d[3])
        : "r"(a[0]), "r"(a[1]), "r"(a[2]), "r"(a[3]), "r"(b[0]), "r"(b[1]));
}

// Pair-permuted + XOR-swizzled A-operand layout.
// Element (row,k) -> row*KS + 2*g + slot, where granule g holds pair (k, k+4),
// g = ((k>>3)*4 + (k&3)) ^ ((row&3)<<2), slot = (k>>2)&1.
// mma load for k-step ks: LDS.64 (float2) at f2-index row*(KS/2) + ((ks^(row&3))<<2) + tq.
__device__ __forceinline__ int swz_idx(int row, int k, int KS) {
    int g = (((k >> 3) << 2) | (k & 3)) ^ ((row & 3) << 2);
    return row * KS + (g << 1) + ((k >> 2) & 1);
}

// ---------------------------------------------------------------------------
// Kernel A: ret = LayerNorm(gelu(gelu(X@W1+b1)@W2+b2) + X)
// 512 threads = 16 warps (4x4), CTA tile 128 tokens.
// H produced/consumed in 4 chunks of 64 cols.
// ---------------------------------------------------------------------------
__global__ __launch_bounds__(512, 1)
void fused_main_kernel(const float* __restrict__ src,
                       const float* __restrict__ W1, const float* __restrict__ b1,
                       const float* __restrict__ W2, const float* __restrict__ b2,
                       const float* __restrict__ gamma, const float* __restrict__ beta,
                       float* __restrict__ out_ret)
{
    extern __shared__ float sm[];
    float* Xf  = sm;               // [128][128] swizzled tf32      16384
    float* Hs  = Xf  + 16384;      // [128][64]  swizzled tf32       8192
    float* W1f = Hs  + 8192;       // [64][132]                      8448
    float* W2f = W1f + 8448;       // [128][68]                      8704
    float* Ps  = W2f + 8704;       // [128][4] float2 partials       1024
    float* b1s = Ps  + 1024;       // 256
    float* b2s = b1s + 256;        // 128
    float* gs  = b2s + 128;        // 128
    float* bs  = gs  + 128;        // 128

    const int tid   = threadIdx.x;
    const int lane  = tid & 31, wid = tid >> 5;
    const int group = lane >> 2, tq = lane & 3;
    const int wm    = wid & 3,  wn  = wid >> 2;
    const int g3    = group & 3;
    const int r0    = wm * 32 + group;

    const int s  = blockIdx.y;
    const int b0 = blockIdx.x * 128;
    const float* Xg = src + ((size_t)s * 2048 + b0) * 128;

    // stage X tile (tf32, swizzled)
    for (int i = tid; i < 4096; i += 512) {
        int row = i >> 5, c4 = i & 31;
        float4 v = reinterpret_cast<const float4*>(Xg + row * 128)[c4];
        int k = c4 * 4;
        Xf[swz_idx(row, k,     128)] = tf32f(v.x);
        Xf[swz_idx(row, k + 1, 128)] = tf32f(v.y);
        Xf[swz_idx(row, k + 2, 128)] = tf32f(v.z);
        Xf[swz_idx(row, k + 3, 128)] = tf32f(v.w);
    }
    if (tid < 256) b1s[tid] = b1[tid];
    if (tid < 128) { b2s[tid] = b2[tid]; gs[tid] = gamma[tid]; bs[tid] = beta[tid]; }

    float acc[8][4];
#pragma unroll
    for (int i = 0; i < 8; i++) { acc[i][0] = acc[i][1] = acc[i][2] = acc[i][3] = 0.f; }

    const float2* Xf2 = reinterpret_cast<const float2*>(Xf);
    const float2* Hs2 = reinterpret_cast<const float2*>(Hs);

    for (int c = 0; c < 4; ++c) {
        // ---- stage W1 chunk (cols c*64..+64) and W2 chunk (rows c*64..+64) ----
        for (int i = tid; i < 8192; i += 512) {
            int k = i >> 6, n = i & 63;
            W1f[n * 132 + k] = tf32f(W1[k * 256 + c * 64 + n]);
        }
        for (int i = tid; i < 8192; i += 512) {
            int k = i >> 7, n = i & 127;
            W2f[n * 68 + k] = tf32f(W2[(c * 64 + k) * 128 + n]);
        }
        __syncthreads();

        // ---- GEMM1: Hc = X @ W1c, warp tile 32x16, K=128 ----
        float ha[4][4];
#pragma unroll
        for (int i = 0; i < 4; i++) { ha[i][0] = ha[i][1] = ha[i][2] = ha[i][3] = 0.f; }

        float2 ab[2][4]; float bbv[2][2][2];
        {
            int t = (g3 << 2) + tq;  // ks=0
            ab[0][0] = Xf2[r0 * 64 + t];        ab[0][1] = Xf2[r0 * 64 + 512 + t];
            ab[0][2] = Xf2[r0 * 64 + 1024 + t]; ab[0][3] = Xf2[r0 * 64 + 1536 + t];
            int nb = wn * 16 + group;
            bbv[0][0][0] = W1f[nb * 132 + tq];       bbv[0][0][1] = W1f[nb * 132 + tq + 4];
            bbv[0][1][0] = W1f[(nb + 8) * 132 + tq]; bbv[0][1][1] = W1f[(nb + 8) * 132 + tq + 4];
        }
#pragma unroll
        for (int ks = 0; ks < 16; ks++) {
            int cur = ks & 1, nxt = cur ^ 1;
            if (ks < 15) {
                int k1 = ks + 1;
                int t = ((k1 ^ g3) << 2) + tq;
                ab[nxt][0] = Xf2[r0 * 64 + t];        ab[nxt][1] = Xf2[r0 * 64 + 512 + t];
                ab[nxt][2] = Xf2[r0 * 64 + 1024 + t]; ab[nxt][3] = Xf2[r0 * 64 + 1536 + t];
                int nb = wn * 16 + group, ko = k1 * 8 + tq;
                bbv[nxt][0][0] = W1f[nb * 132 + ko];       bbv[nxt][0][1] = W1f[nb * 132 + ko + 4];
                bbv[nxt][1][0] = W1f[(nb + 8) * 132 + ko]; bbv[nxt][1][1] = W1f[(nb + 8) * 132 + ko + 4];
            }
            unsigned a0[4] = {__float_as_uint(ab[cur][0].x), __float_as_uint(ab[cur][1].x),
                              __float_as_uint(ab[cur][0].y), __float_as_uint(ab[cur][1].y)};
            unsigned a1[4] = {__float_as_uint(ab[cur][2].x), __float_as_uint(ab[cur][3].x),
                              __float_as_uint(ab[cur][2].y), __float_as_uint(ab[cur][3].y)};
#pragma unroll
            for (int nt = 0; nt < 2; nt++) {
                unsigned bf[2] = {__float_as_uint(bbv[cur][nt][0]), __float_as_uint(bbv[cur][nt][1])};
                mma8(ha[nt],     a0, bf);
                mma8(ha[2 + nt], a1, bf);
            }
        }

        // ---- bias + gelu -> Hs (swizzled tf32) ----
#pragma unroll
        for (int mt = 0; mt < 2; mt++) {
#pragma unroll
            for (int nt = 0; nt < 2; nt++) {
                int hcol = wn * 16 + nt * 8 + 2 * tq;
                float bi0 = b1s[c * 64 + hcol], bi1 = b1s[c * 64 + hcol + 1];
                int rA = r0 + mt * 16, rB = rA + 8;
                float* hv = ha[mt * 2 + nt];
                Hs[swz_idx(rA, hcol,     64)] = tf32f(gelu_exact(hv[0] + bi0));
                Hs[swz_idx(rA, hcol + 1, 64)] = tf32f(gelu_exact(hv[1] + bi1));
                Hs[swz_idx(rB, hcol,     64)] = tf32f(gelu_exact(hv[2] + bi0));
                Hs[swz_idx(rB, hcol + 1, 64)] = tf32f(gelu_exact(hv[3] + bi1));
            }
        }
        __syncthreads();

        // ---- GEMM2: acc += Hc @ W2c, warp tile 32x32, K=64 ----
        float2 ab2[2][4]; float bb2[2][4][2];
        {
            int t = (g3 << 2) + tq;  // ks=0
            ab2[0][0] = Hs2[r0 * 32 + t];       ab2[0][1] = Hs2[r0 * 32 + 256 + t];
            ab2[0][2] = Hs2[r0 * 32 + 512 + t]; ab2[0][3] = Hs2[r0 * 32 + 768 + t];
            int nb = wn * 32 + group;
#pragma unroll
            for (int nt = 0; nt < 4; nt++) {
                bb2[0][nt][0] = W2f[(nb + nt * 8) * 68 + tq];
                bb2[0][nt][1] = W2f[(nb + nt * 8) * 68 + tq + 4];
            }
        }
#pragma unroll
        for (int ks = 0; ks < 8; ks++) {
            int cur = ks & 1, nxt = cur ^ 1;
            if (ks < 7) {
                int k1 = ks + 1, t = ((k1 ^ g3) << 2) + tq;
                ab2[nxt][0] = Hs2[r0 * 32 + t];       ab2[nxt][1] = Hs2[r0 * 32 + 256 + t];
                ab2[nxt][2] = Hs2[r0 * 32 + 512 + t]; ab2[nxt][3] = Hs2[r0 * 32 + 768 + t];
                int nb = wn * 32 + group, ko = k1 * 8 + tq;
#pragma unroll
                for (int nt = 0; nt < 4; nt++) {
                    bb2[nxt][nt][0] = W2f[(nb + nt * 8) * 68 + ko];
                    bb2[nxt][nt][1] = W2f[(nb + nt * 8) * 68 + ko + 4];
                }
            }
            unsigned a0[4] = {__float_as_uint(ab2[cur][0].x), __float_as_uint(ab2[cur][1].x),
                              __float_as_uint(ab2[cur][0].y), __float_as_uint(ab2[cur][1].y)};
            unsigned a1[4] = {__float_as_uint(ab2[cur][2].x), __float_as_uint(ab2[cur][3].x),
                              __float_as_uint(ab2[cur][2].y), __float_as_uint(ab2[cur][3].y)};
#pragma unroll
            for (int nt = 0; nt < 4; nt++) {
                unsigned bf[2] = {__float_as_uint(bb2[cur][nt][0]), __float_as_uint(bb2[cur][nt][1])};
                mma8(acc[nt],     a0, bf);
                mma8(acc[4 + nt], a1, bf);
            }
        }
        __syncthreads();
    }

    // ---- epilogue: r = gelu(acc+b2) + X (X re-read from gmem); LayerNorm ----
    float sums[4] = {0, 0, 0, 0}, sqs[4] = {0, 0, 0, 0};
    const float2* Xg2 = reinterpret_cast<const float2*>(Xg);
#pragma unroll
    for (int mt = 0; mt < 2; mt++) {
#pragma unroll
        for (int nt = 0; nt < 4; nt++) {
            int col = wn * 32 + nt * 8 + 2 * tq;
            int rA = r0 + mt * 16, rB = rA + 8;
            float2 xa = Xg2[rA * 64 + (col >> 1)];
            float2 xb = Xg2[rB * 64 + (col >> 1)];
            float* av = acc[mt * 4 + nt];
            av[0] = gelu_exact(av[0] + b2s[col])     + xa.x;
            av[1] = gelu_exact(av[1] + b2s[col + 1]) + xa.y;
            av[2] = gelu_exact(av[2] + b2s[col])     + xb.x;
            av[3] = gelu_exact(av[3] + b2s[col + 1]) + xb.y;
            sums[mt * 2]     += av[0] + av[1]; sqs[mt * 2]     += av[0] * av[0] + av[1] * av[1];
            sums[mt * 2 + 1] += av[2] + av[3]; sqs[mt * 2 + 1] += av[2] * av[2] + av[3] * av[3];
        }
    }
#pragma unroll
    for (int j = 0; j < 4; j++) {
#pragma unroll
        for (int o = 1; o < 4; o <<= 1) {
            sums[j] += __shfl_xor_sync(0xffffffffu, sums[j], o);
            sqs[j]  += __shfl_xor_sync(0xffffffffu, sqs[j],  o);
        }
    }
    if (tq == 0) {
        float2* Ps2 = reinterpret_cast<float2*>(Ps);
#pragma unroll
        for (int j = 0; j < 4; j++) {
            int row = r0 + j * 8;
            Ps2[row * 4 + wn] = make_float2(sums[j], sqs[j]);
        }
    }
    __syncthreads();
    float mus[4], rss[4];
    {
        const float2* Ps2 = reinterpret_cast<const float2*>(Ps);
#pragma unroll
        for (int j = 0; j < 4; j++) {
            int row = r0 + j * 8;
            float ssum = 0.f, ssq = 0.f;
#pragma unroll
            for (int w = 0; w < 4; w++) { float2 p = Ps2[row * 4 + w]; ssum += p.x; ssq += p.y; }
            float mu  = ssum * (1.f / 128.f);
            float var = ssq * (1.f / 128.f) - mu * mu;
            mus[j] = mu; rss[j] = rsqrtf(var + 1e-5f);
        }
    }
    float2* outg2 = reinterpret_cast<float2*>(out_ret + ((size_t)s * 2048 + b0) * 128);
#pragma unroll
    for (int mt = 0; mt < 2; mt++) {
#pragma unroll
        for (int nt = 0; nt < 4; nt++) {
            int col = wn * 32 + nt * 8 + 2 * tq;
            int rA = r0 + mt * 16, rB = rA + 8;
            float* av = acc[mt * 4 + nt];
            float muA = mus[mt * 2],     rsA = rss[mt * 2];
            float muB = mus[mt * 2 + 1], rsB = rss[mt * 2 + 1];
            float2 o0 = make_float2((av[0] - muA) * rsA * gs[col]     + bs[col],
                                    (av[1] - muA) * rsA * gs[col + 1] + bs[col + 1]);
            float2 o1 = make_float2((av[2] - muB) * rsB * gs[col]     + bs[col],
                                    (av[3] - muB) * rsB * gs[col + 1] + bs[col + 1]);
            outg2[rA * 64 + (col >> 1)] = o0;
            outg2[rB * 64 + (col >> 1)] = o1;
        }
    }
}

// ---------------------------------------------------------------------------
// Kernel B: diffs[s-1] = gelu([X_{s-1} | X_s] @ Wb + bb)
// 512 threads = 16 warps (4x4), warp tile 32x32, K=256 in two 128 halves.
// ---------------------------------------------------------------------------
__global__ __launch_bounds__(512, 1)
void bracket_kernel(const float* __restrict__ src,
                    const float* __restrict__ Wb, const float* __restrict__ bb,
                    float* __restrict__ out_diffs, float* __restrict__ cond)
{
    extern __shared__ float sm[];
    float* Xpf = sm;               // [128][128] swizzled tf32   16384
    float* Xcf = Xpf + 16384;      // 16384
    float* Wbf = Xcf + 16384;      // [128][132]                 16896
    float* bbs = Wbf + 16896;      // 128

    const int tid   = threadIdx.x;
    const int lane  = tid & 31, wid = tid >> 5;
    const int group = lane >> 2, tq = lane & 3;
    const int wm    = wid & 3,  wn  = wid >> 2;
    const int g3    = group & 3;
    const int r0    = wm * 32 + group;

    const int s  = blockIdx.y + 1;
    const int b0 = blockIdx.x * 128;
    if (blockIdx.x == 0 && blockIdx.y == 0 && tid < 3) cond[tid] = 0.f;

    const float* Xgp = src + ((size_t)(s - 1) * 2048 + b0) * 128;
    const float* Xgc = src + ((size_t)s * 2048 + b0) * 128;

    for (int i = tid; i < 4096; i += 512) {
        int row = i >> 5, c4 = i & 31, k = c4 * 4;
        float4 vp = reinterpret_cast<const float4*>(Xgp + row * 128)[c4];
        float4 vc = reinterpret_cast<const float4*>(Xgc + row * 128)[c4];
        Xpf[swz_idx(row, k,     128)] = tf32f(vp.x);
        Xpf[swz_idx(row, k + 1, 128)] = tf32f(vp.y);
        Xpf[swz_idx(row, k + 2, 128)] = tf32f(vp.z);
        Xpf[swz_idx(row, k + 3, 128)] = tf32f(vp.w);
        Xcf[swz_idx(row, k,     128)] = tf32f(vc.x);
        Xcf[swz_idx(row, k + 1, 128)] = tf32f(vc.y);
        Xcf[swz_idx(row, k + 2, 128)] = tf32f(vc.z);
        Xcf[swz_idx(row, k + 3, 128)] = tf32f(vc.w);
    }
    if (tid < 128) bbs[tid] = bb[tid];

    float acc[8][4];
#pragma unroll
    for (int i = 0; i < 8; i++) { acc[i][0] = acc[i][1] = acc[i][2] = acc[i][3] = 0.f; }

    for (int h = 0; h < 2; ++h) {
        // stage Wb half: rows [h*128, h*128+128)
        for (int i = tid; i < 16384; i += 512) {
            int k = i >> 7, n = i & 127;
            Wbf[n * 132 + k] = tf32f(Wb[(h * 128 + k) * 128 + n]);
        }
        __syncthreads();

        const float2* A2 = reinterpret_cast<const float2*>(h ? Xcf : Xpf);

        float2 ab[2][4]; float bbv[2][4][2];
        {
            int t = (g3 << 2) + tq;  // ks=0
            ab[0][0] = A2[r0 * 64 + t];        ab[0][1] = A2[r0 * 64 + 512 + t];
            ab[0][2] = A2[r0 * 64 + 1024 + t]; ab[0][3] = A2[r0 * 64 + 1536 + t];
            int nb = wn * 32 + group;
#pragma unroll
            for (int nt = 0; nt < 4; nt++) {
                bbv[0][nt][0] = Wbf[(nb + nt * 8) * 132 + tq];
                bbv[0][nt][1] = Wbf[(nb + nt * 8) * 132 + tq + 4];
            }
        }
#pragma unroll
        for (int ks = 0; ks < 16; ks++) {
            int cur = ks & 1, nxt = cur ^ 1;
            if (ks < 15) {
                int k1 = ks + 1, t = ((k1 ^ g3) << 2) + tq;
                ab[nxt][0] = A2[r0 * 64 + t];        ab[nxt][1] = A2[r0 * 64 + 512 + t];
                ab[nxt][2] = A2[r0 * 64 + 1024 + t]; ab[nxt][3] = A2[r0 * 64 + 1536 + t];
                int nb = wn * 32 + group, ko = k1 * 8 + tq;
#pragma unroll
                for (int nt = 0; nt < 4; nt++) {
                    bbv[nxt][nt][0] = Wbf[(nb + nt * 8) * 132 + ko];
                    bbv[nxt][nt][1] = Wbf[(nb + nt * 8) * 132 + ko + 4];
                }
            }
            unsigned a0[4] = {__float_as_uint(ab[cur][0].x), __float_as_uint(ab[cur][1].x),
                              __float_as_uint(ab[cur][0].y), __float_as_uint(ab[cur][1].y)};
            unsigned a1[4] = {__float_as_uint(ab[cur][2].x), __float_as_uint(ab[cur][3].x),
                              __float_as_uint(ab[cur][2].y), __float_as_uint(ab[cur][3].y)};
#pragma unroll
            for (int nt = 0; nt < 4; nt++) {
                unsigned bf[2] = {__float_as_uint(bbv[cur][nt][0]), __float_as_uint(bbv[cur][nt][1])};
                mma8(acc[nt],     a0, bf);
                mma8(acc[4 + nt], a1, bf);
            }
        }
        __syncthreads();
    }

    // epilogue: gelu(acc + bb) -> diffs
    float2* og2 = reinterpret_cast<float2*>(out_diffs + ((size_t)(s - 1) * 2048 + b0) * 128);
#pragma unroll
    for (int mt = 0; mt < 2; mt++) {
#pragma unroll
        for (int nt = 0; nt < 4; nt++) {
            int col = wn * 32 + nt * 8 + 2 * tq;
            int rA = r0 + mt * 16, rB = rA + 8;
            float bi0 = bbs[col], bi1 = bbs[col + 1];
            float* av = acc[mt * 4 + nt];
            float2 o0 = make_float2(gelu_exact(av[0] + bi0), gelu_exact(av[1] + bi1));
            float2 o1 = make_float2(gelu_exact(av[2] + bi0), gelu_exact(av[3] + bi1));
            og2[rA * 64 + (col >> 1)] = o0;
            og2[rB * 64 + (col >> 1)] = o1;
        }
    }
}

// ---------------------------------------------------------------------------
// launcher
// ---------------------------------------------------------------------------
extern "C" void kernel_launch(void* const* d_in, const int* in_sizes, int n_in,
                              void* d_out, int out_size)
{
    const float* src   = (const float*)d_in[0];
    const float* Wb    = (const float*)d_in[1];
    const float* bb    = (const float*)d_in[2];
    const float* W1    = (const float*)d_in[3];
    const float* b1    = (const float*)d_in[4];
    const float* W2    = (const float*)d_in[5];
    const float* b2    = (const float*)d_in[6];
    const float* gamma = (const float*)d_in[7];
    const float* beta  = (const float*)d_in[8];
    float* out = (float*)d_out;

    const int smA = (16384 + 8192 + 8448 + 8704 + 1024 + 256 + 128 + 128 + 128) * 4; // 173568
    const int smB = (16384 + 16384 + 16896 + 128) * 4;                               // 199168

    cudaFuncSetAttribute(fused_main_kernel, cudaFuncAttributeMaxDynamicSharedMemorySize, smA);
    cudaFuncSetAttribute(bracket_kernel,    cudaFuncAttributeMaxDynamicSharedMemorySize, smB);

    dim3 gA(16, 256);
    dim3 gB(16, 255);

    fused_main_kernel<<<gA, 512, smA>>>(src, W1, b1, W2, b2, gamma, beta, out);
    bracket_kernel<<<gB, 512, smB>>>(src, Wb, bb,
                                     out + RET_ELEMS,
                                     out + RET_ELEMS + DIFF_ELEMS);
}